// round 16
// baseline (speedup 1.0000x reference)
#include <cuda_runtime.h>
#include <cuda_bf16.h>
#include <cuda_fp16.h>
#include <math.h>
#include <stdint.h>

// Problem constants
#define NB 256        // batch B
#define NN 1024       // N
#define NK 64         // K
#define INV_TEMP 5.0f // 1/0.2
#define LN_EPS 1e-5f
#define A_SCALE 4096.0f
#define A_INV_SCALE 2.44140625e-4f
#define WP_SCALE 16384.0f
#define WP_INV (1.0f / 16384.0f)
#define C_N 9.765625e-4f   // 1/1024 exact
#define C_K 0.015625f      // 1/64 exact

// Scratch (static device globals; allocation inside kernel_launch is forbidden)
static __device__ float g_S[NN * NN];                    // row-stochastic P 4 MB
static __device__ __half g_WT[(size_t)NN * NK * NK];     // (W - 1/64)^T *16384 fp16 [n][o][i] 8 MB
static __device__ __half g_XLh[(size_t)NB * NN * NK];    // x_local fp16 [b][n][k] 32 MB
static __device__ __half g_Yh[(size_t)NB * NK * NN];     // Y fp16 [r][m] 32 MB
static __device__ __half g_STh[NN * NN];                 // (A - 1/1024)^T * 4096, fp16 [n][m] 2 MB
static __device__ float g_SY[NB * NK];                   // per-row sums of Y (exact fp32)

// ============================ PTX helpers (sm_80-era only!) ============================
__device__ __forceinline__ uint32_t smem_u32(const void* p) {
    uint32_t a;
    asm("{ .reg .u64 t; cvta.to.shared.u64 t, %1; cvt.u32.u64 %0, t; }" : "=r"(a) : "l"(p));
    return a;
}
__device__ __forceinline__ void cpa16(uint32_t s, const void* g) {
    asm volatile("cp.async.cg.shared.global [%0], [%1], 16;" :: "r"(s), "l"(g));
}
__device__ __forceinline__ void ldm4(uint32_t* r, uint32_t a) {
    asm volatile("ldmatrix.sync.aligned.m8n8.x4.shared.b16 {%0,%1,%2,%3}, [%4];"
                 : "=r"(r[0]), "=r"(r[1]), "=r"(r[2]), "=r"(r[3]) : "r"(a));
}
__device__ __forceinline__ void mma_fp16(float* d, const uint32_t* a, const uint32_t* b) {
    asm volatile(
        "mma.sync.aligned.m16n8k16.row.col.f32.f16.f16.f32 "
        "{%0,%1,%2,%3}, {%4,%5,%6,%7}, {%8,%9}, {%0,%1,%2,%3};"
        : "+f"(d[0]), "+f"(d[1]), "+f"(d[2]), "+f"(d[3])
        : "r"(a[0]), "r"(a[1]), "r"(a[2]), "r"(a[3]), "r"(b[0]), "r"(b[1]));
}

// ---------------------------------------------------------------------------
// Kernel 1: row pass. P[row] = exp(logits/T) / rowsum — linear domain, __expf.
// ---------------------------------------------------------------------------
__global__ void k_sink_row(const float* __restrict__ logits) {
    const int row = blockIdx.x;
    const int t = threadIdx.x;
    const float* rp = logits + (size_t)row * NN;
    float e[4];
    float acc = 0.f;
#pragma unroll
    for (int q = 0; q < 4; ++q) {
        e[q] = __expf(rp[t + 256 * q] * INV_TEMP);
        acc += e[q];
    }
    __shared__ float red[256];
    red[t] = acc;
    __syncthreads();
    for (int s = 128; s > 0; s >>= 1) {
        if (t < s) red[t] += red[t + s];
        __syncthreads();
    }
    const float rinv = 1.0f / red[0];
    float* op = g_S + (size_t)row * NN;
#pragma unroll
    for (int q = 0; q < 4; ++q) op[t + 256 * q] = e[q] * rinv;
}

// ---------------------------------------------------------------------------
// Kernel 2: column normalize + emit STh[n][m] = (P[m][n]/colsum - 1/1024)*4096
// directly (transposed, fp16) via a 135 KB smem buffer. No exp at all.
// ---------------------------------------------------------------------------
#define CP 33
__global__ void __launch_bounds__(256) k_sink_colT() {
    extern __shared__ float buf[];  // [1024][CP]
    const int c0 = blockIdx.x * 32;
    const int t = threadIdx.x;
    const int c = t & 31, ry = t >> 5;
    float csum = 0.f;
    for (int m = ry; m < NN; m += 8) {
        float v = g_S[(size_t)m * NN + c0 + c];
        buf[m * CP + c] = v;
        csum += v;
    }
    __shared__ float ss[8][32];
    __shared__ float cinv[32];
    ss[ry][c] = csum;
    __syncthreads();
    if (t < 32) {
        float S = 0.f;
#pragma unroll
        for (int q = 0; q < 8; ++q) S += ss[q][t];
        cinv[t] = 1.0f / S;
    }
    __syncthreads();
    const int w = t >> 5, L = t & 31;
#pragma unroll
    for (int j = 0; j < 4; ++j) {
        const int cc = w * 4 + j;
        const float ci = cinv[cc] * A_SCALE;  // STh = P*ci - 4  (A_SCALE/1024 = 4)
        __half2* op = (__half2*)(g_STh + (size_t)(c0 + cc) * NN);
#pragma unroll
        for (int q = 0; q < 16; ++q) {
            const int m = 2 * L + 64 * q;
            float a = buf[m * CP + cc] * ci - 4.0f;
            float b = buf[(m + 1) * CP + cc] * ci - 4.0f;
            op[m >> 1] = __floats2half2_rn(a, b);
        }
    }
}

// ---------------------------------------------------------------------------
// Kernel 3: per-block sinkhorn of W1.W_V, linear domain (__expf once, 2 rcps).
// Emits W'^T = (W - 1/64)*WP_SCALE fp16 [n][o][i].
// ---------------------------------------------------------------------------
__global__ void k_wsink(const float* __restrict__ W1, const float* __restrict__ WV) {
    const int n = blockIdx.x;
    const int t = threadIdx.x;
    __shared__ float L[64][65];
    __shared__ float w1[8];
    __shared__ float rinv[64], cinv[64];
    __shared__ float redc[4][64];
    if (t < 8) w1[t] = W1[n * 8 + t];
    __syncthreads();
#pragma unroll
    for (int q = 0; q < 16; ++q) {
        int idx = t + 256 * q;
        float acc = 0.f;
#pragma unroll
        for (int k = 0; k < 8; ++k) acc += w1[k] * WV[k * 4096 + idx];
        L[idx >> 6][idx & 63] = __expf(acc * INV_TEMP);
    }
    __syncthreads();
    {
        const int r = t >> 2, j0 = (t & 3) * 16;
        float s = 0.f;
#pragma unroll
        for (int e = 0; e < 16; ++e) s += L[r][j0 + e];
        s += __shfl_xor_sync(0xffffffffu, s, 1);
        s += __shfl_xor_sync(0xffffffffu, s, 2);
        if ((t & 3) == 0) rinv[r] = 1.0f / s;
    }
    __syncthreads();
    {
        const int o = t & 63, p = t >> 6;
        float cs = 0.f;
#pragma unroll
        for (int e = 0; e < 16; ++e) {
            const int d = p * 16 + e;
            float f = L[d][o] * rinv[d];
            L[d][o] = f;
            cs += f;
        }
        redc[p][o] = cs;
    }
    __syncthreads();
    if (t < 64)
        cinv[t] = 1.0f / ((redc[0][t] + redc[1][t]) + (redc[2][t] + redc[3][t]));
    __syncthreads();
    __half* wt = g_WT + (size_t)n * 4096;
#pragma unroll
    for (int q = 0; q < 16; ++q) {
        int idx = t + 256 * q;
        int o = idx >> 6, d = idx & 63;
        wt[idx] = __float2half((L[d][o] * cinv[o] - C_K) * WP_SCALE);
    }
}

// ---------------------------------------------------------------------------
// Kernel 4: x_local = sx/64 + (x@W'^T)/16384 via fp16 MMA. One n per block,
// 128 threads, HALF of b (128 rows, selected by b_off): 4 resident blocks/SM
// give 4 overlapping load phases. All LDGs issued before the single sync.
// smem: Xs fp16 [128][72] | Ws fp16 [64][72] | sxs[128] fp32  (= 28160 B)
// ---------------------------------------------------------------------------
#define XL_SMEM (128 * 72 * 2 + 64 * 72 * 2 + 128 * 4)
__global__ void __launch_bounds__(128) k_xlocal(const float* __restrict__ x, int b_off) {
    extern __shared__ char dsm[];
    __half* Xs = (__half*)dsm;                 // [128][72]
    __half* Ws = Xs + 128 * 72;                // [64][72]
    float* sxs = (float*)(Ws + 64 * 72);       // [128]

    const int n = blockIdx.x;
    const int t = threadIdx.x;
    const int L = t & 31, w = t >> 5;

    // WT tile once per block
    {
        const __half* wp = g_WT + (size_t)n * 4096;
#pragma unroll
        for (int q = 0; q < 4; ++q) {
            int u = t + 128 * q;
            int row = u >> 3, c8 = (u & 7) * 8;
            *(uint4*)(Ws + row * 72 + c8) = *(const uint4*)(wp + u * 8);
        }
    }

    // X: 4 threads per row, 4 row-passes — 16 independent LDG.128 per thread.
    {
        const int rbase = t >> 2, c0 = (t & 3) * 16;
#pragma unroll
        for (int q = 0; q < 4; ++q) {
            const int row = rbase + 32 * q;  // 0..127
            const float* xp = x + (size_t)(b_off + row) * (NN * NK) + n * NK + c0;
            float4 v0 = *(const float4*)(xp + 0);
            float4 v1 = *(const float4*)(xp + 4);
            float4 v2 = *(const float4*)(xp + 8);
            float4 v3 = *(const float4*)(xp + 12);
            float s = ((v0.x + v0.y) + (v0.z + v0.w)) + ((v1.x + v1.y) + (v1.z + v1.w)) +
                      ((v2.x + v2.y) + (v2.z + v2.w)) + ((v3.x + v3.y) + (v3.z + v3.w));
            __half2* xs = (__half2*)(Xs + row * 72 + c0);
            xs[0] = __floats2half2_rn(v0.x, v0.y);
            xs[1] = __floats2half2_rn(v0.z, v0.w);
            xs[2] = __floats2half2_rn(v1.x, v1.y);
            xs[3] = __floats2half2_rn(v1.z, v1.w);
            xs[4] = __floats2half2_rn(v2.x, v2.y);
            xs[5] = __floats2half2_rn(v2.z, v2.w);
            xs[6] = __floats2half2_rn(v3.x, v3.y);
            xs[7] = __floats2half2_rn(v3.z, v3.w);
            s += __shfl_xor_sync(0xffffffffu, s, 1);
            s += __shfl_xor_sync(0xffffffffu, s, 2);
            if ((t & 3) == 0) sxs[row] = s;
        }
    }
    __syncthreads();

    // MMA: warp w owns local b rows [w*32, w*32+32), all 64 k.
    const int m0 = w * 32;
    const uint32_t xb = smem_u32(Xs), wb = smem_u32(Ws);
    const uint32_t a_l = xb + (uint32_t)((m0 + (L & 15)) * 144 + (L >> 4) * 16);
    const uint32_t b_l = wb + (uint32_t)(((L & 7) + ((L & 16) ? 8 : 0)) * 144 +
                                         ((L & 8) ? 16 : 0));
    float acc[2][8][4] = {};
#pragma unroll
    for (int ks = 0; ks < 4; ++ks) {
        uint32_t ah[2][4], bh[4][4];
#pragma unroll
        for (int mt = 0; mt < 2; ++mt)
            ldm4(ah[mt], a_l + ks * 32 + mt * (16 * 144));
#pragma unroll
        for (int bj = 0; bj < 4; ++bj)
            ldm4(bh[bj], b_l + ks * 32 + bj * (16 * 144));
#pragma unroll
        for (int mt = 0; mt < 2; ++mt)
#pragma unroll
            for (int nj = 0; nj < 8; ++nj)
                mma_fp16(acc[mt][nj], ah[mt], &bh[nj >> 1][(nj & 1) * 2]);
    }

    // Epilogue: xl = acc*WP_INV + sx/64, fp16 [b][n][k]
    const int r = L >> 2;
#pragma unroll
    for (int mt = 0; mt < 2; ++mt) {
        const int bl = m0 + mt * 16 + r;  // local row
        const float sx0 = sxs[bl] * C_K, sx1 = sxs[bl + 8] * C_K;
        __half* xl0 = g_XLh + ((size_t)(b_off + bl) * NN + n) * NK;
        __half* xl1 = xl0 + (size_t)8 * NN * NK;
#pragma unroll
        for (int nj = 0; nj < 8; ++nj) {
            const int k = nj * 8 + (L & 3) * 2;
            *(__half2*)(xl0 + k) =
                __floats2half2_rn(acc[mt][nj][0] * WP_INV + sx0, acc[mt][nj][1] * WP_INV + sx0);
            *(__half2*)(xl1 + k) =
                __floats2half2_rn(acc[mt][nj][2] * WP_INV + sx1, acc[mt][nj][3] * WP_INV + sx1);
        }
    }
}

// ---------------------------------------------------------------------------
// Kernel 5: layernorm over n (per (b,k)) + transpose, k-chunk 8 (33 KB smem).
// Reads fp16 XL, emits fp16 Y [r][m] + exact fp32 row sums. b_off selects half.
// ---------------------------------------------------------------------------
#define LBUF 1025
__global__ void __launch_bounds__(256) k_lnt(const float* __restrict__ gamma2,
                                             const float* __restrict__ beta2, int b_off) {
    extern __shared__ float buf[];  // [8][LBUF]
    const int b = b_off + blockIdx.x;
    const int k0 = blockIdx.y * 8;
    const int t = threadIdx.x;
    const __half* base = g_XLh + (size_t)b * NN * NK + k0;
#pragma unroll
    for (int q = 0; q < 4; ++q) {
        const int nn = t + 256 * q;
        uint4 v = *(const uint4*)(base + (size_t)nn * NK);
        const __half2* h = (const __half2*)&v;
#pragma unroll
        for (int j = 0; j < 4; ++j) {
            float2 f = __half22float2(h[j]);
            buf[(2 * j) * LBUF + nn] = f.x;
            buf[(2 * j + 1) * LBUF + nn] = f.y;
        }
    }
    __syncthreads();
    __shared__ float ps[32][9], ps2[32][9], mu[8], rs[8];
    {
        const int kc = t & 7, nr = t >> 3;
        float s = 0.f, s2 = 0.f;
        for (int nn = nr; nn < NN; nn += 32) {
            float v = buf[kc * LBUF + nn];
            s += v;
            s2 += v * v;
        }
        ps[nr][kc] = s;
        ps2[nr][kc] = s2;
    }
    __syncthreads();
    if (t < 8) {
        float S = 0.f, S2 = 0.f;
#pragma unroll
        for (int q = 0; q < 32; ++q) { S += ps[q][t]; S2 += ps2[q][t]; }
        float m = S * (1.0f / NN);
        mu[t] = m;
        rs[t] = rsqrtf(S2 * (1.0f / NN) - m * m + LN_EPS);
    }
    __syncthreads();
    const int L = t & 31, w = t >> 5;
    const float m = mu[w], r = rs[w];
    __half2* yp = (__half2*)(g_Yh + (size_t)(b * NK + k0 + w) * NN);
    float sy = 0.f;
#pragma unroll
    for (int q = 0; q < 16; ++q) {
        const int nn = 2 * L + 64 * q;
        float2 g = *(const float2*)(gamma2 + nn);
        float2 bt = *(const float2*)(beta2 + nn);
        float v0 = (buf[w * LBUF + nn] - m) * r * g.x + bt.x;
        float v1 = (buf[w * LBUF + nn + 1] - m) * r * g.y + bt.y;
        sy += v0 + v1;
        yp[nn >> 1] = __floats2half2_rn(v0, v1);
    }
#pragma unroll
    for (int off = 16; off; off >>= 1) sy += __shfl_xor_sync(0xffffffffu, sy, off);
    if (L == 0) g_SY[b * NK + k0 + w] = sy;
}

// ---------------------------------------------------------------------------
// Kernel 6: single-pass fp16 tensor-core GEMM, 3-stage cp.async pipeline.
//   D[r][n] = sum_m Yh[r][m] * STh[n][m];  out = D/A_SCALE + SY[r]/1024.
// rblk_off selects the r-half (for pipelining with lnt).
// ---------------------------------------------------------------------------
#define T_ROWB 144
#define TILE_B (128 * T_ROWB)
#define STAGE_B (2 * TILE_B)
#define OFF_Y 0u
#define OFF_S ((uint32_t)TILE_B)

__device__ __forceinline__ void g_load_stage(uint32_t st, int r0, int n0, int m0, int t) {
    for (int i = t; i < 1024; i += 256) {
        const int row = i >> 3, q = i & 7;
        const uint32_t so = (uint32_t)(row * T_ROWB + q * 16);
        cpa16(st + OFF_Y + so, g_Yh + (size_t)(r0 + row) * NN + m0 + q * 8);
        cpa16(st + OFF_S + so, g_STh + (size_t)(n0 + row) * NN + m0 + q * 8);
    }
}

__global__ void __launch_bounds__(256) k_gemm_mma(float* __restrict__ out, int rblk_off) {
    extern __shared__ char dsm[];
    const int t = threadIdx.x;
    const int r0 = (blockIdx.x + rblk_off) * 128;
    const int n0 = blockIdx.y * 128;
    __shared__ float s_sy[128];
    if (t < 128) s_sy[t] = g_SY[r0 + t] * C_N;
    const uint32_t sb = smem_u32(dsm);

    g_load_stage(sb, r0, n0, 0, t);
    asm volatile("cp.async.commit_group;" ::: "memory");
    g_load_stage(sb + STAGE_B, r0, n0, 64, t);
    asm volatile("cp.async.commit_group;" ::: "memory");
    g_load_stage(sb + 2 * STAGE_B, r0, n0, 128, t);
    asm volatile("cp.async.commit_group;" ::: "memory");

    const int L = t & 31, w = t >> 5;
    const int wr = (w >> 1) * 32;
    const int wn = (w & 1) * 64;
    const uint32_t a_l = (uint32_t)((wr + (L & 15)) * T_ROWB + ((L >> 4) * 8) * 2);
    const uint32_t b_l = (uint32_t)((wn + (L & 7) + ((L & 16) ? 8 : 0)) * T_ROWB + ((L & 8) ? 16 : 0));

    float acc[2][8][4] = {};
    int stg = 0;

#pragma unroll 1
    for (int c = 0; c < 16; ++c) {
        if (c < 14)       asm volatile("cp.async.wait_group 2;" ::: "memory");
        else if (c == 14) asm volatile("cp.async.wait_group 1;" ::: "memory");
        else              asm volatile("cp.async.wait_group 0;" ::: "memory");
        __syncthreads();
        const uint32_t st = sb + (uint32_t)stg * STAGE_B;
#pragma unroll
        for (int ks = 0; ks < 4; ++ks) {
            uint32_t ah[2][4], bh[4][4];
            const uint32_t ka = st + a_l + ks * 32;
            const uint32_t kb = st + b_l + ks * 32;
#pragma unroll
            for (int mt = 0; mt < 2; ++mt)
                ldm4(ah[mt], ka + OFF_Y + mt * (16 * T_ROWB));
#pragma unroll
            for (int bj = 0; bj < 4; ++bj)
                ldm4(bh[bj], kb + OFF_S + bj * (16 * T_ROWB));
#pragma unroll
            for (int mt = 0; mt < 2; ++mt)
#pragma unroll
                for (int nj = 0; nj < 8; ++nj)
                    mma_fp16(acc[mt][nj], ah[mt], &bh[nj >> 1][(nj & 1) * 2]);
        }
        __syncthreads();
        if (c + 3 < 16) {
            g_load_stage(st, r0, n0, (c + 3) * 64, t);
            asm volatile("cp.async.commit_group;" ::: "memory");
        }
        stg = (stg == 2) ? 0 : stg + 1;
    }

    // Epilogue: acc -> smem [n][r], then coalesced float4 STG.
    float* so = (float*)dsm;
#pragma unroll
    for (int mt = 0; mt < 2; ++mt)
#pragma unroll
        for (int nj = 0; nj < 8; ++nj) {
            const int rl = wr + mt * 16 + (L >> 2);
            const int nl = wn + nj * 8 + (L & 3) * 2;
            so[nl * 132 + rl]           = acc[mt][nj][0];
            so[(nl + 1) * 132 + rl]     = acc[mt][nj][1];
            so[nl * 132 + rl + 8]       = acc[mt][nj][2];
            so[(nl + 1) * 132 + rl + 8] = acc[mt][nj][3];
        }
    __syncthreads();
    for (int i = t; i < 4096; i += 256) {
        const int n = i >> 5;
        const int rq = (i & 31) * 4;
        float4 v;
        v.x = so[n * 132 + rq]     * A_INV_SCALE + s_sy[rq];
        v.y = so[n * 132 + rq + 1] * A_INV_SCALE + s_sy[rq + 1];
        v.z = so[n * 132 + rq + 2] * A_INV_SCALE + s_sy[rq + 2];
        v.w = so[n * 132 + rq + 3] * A_INV_SCALE + s_sy[rq + 3];
        const int r = r0 + rq;
        *(float4*)(out + (size_t)(r >> 6) * (NN * NK) + (size_t)(n0 + n) * NK + (r & 63)) = v;
    }
}

// ---------------------------------------------------------------------------
// Launch: fork-join DAG.
//   side stream sA:  sink_row -> colT                (independent A-path)
//   main stream:     wsink -> xlocal_h0 -> xlocal_h1 -> gemm_h0 -> gemm_h1
//   side stream sL:  lnt_h0 (after xl_h0, || xl_h1), lnt_h1 (|| gemm_h0)
// All side streams rejoin the origin stream via events before return
// (required for graph capture).
// ---------------------------------------------------------------------------
extern "C" void kernel_launch(void* const* d_in, const int* in_sizes, int n_in,
                              void* d_out, int out_size) {
    (void)in_sizes; (void)n_in; (void)out_size;
    const float* x        = (const float*)d_in[0];  // [B, N*K]
    const float* A_logits = (const float*)d_in[1];  // [N, N]
    const float* W1       = (const float*)d_in[2];  // [N, 8]
    const float* WV       = (const float*)d_in[3];  // [8, K, K]
    const float* gamma2   = (const float*)d_in[4];  // [N]
    const float* beta2    = (const float*)d_in[5];  // [N]
    float* out = (float*)d_out;

    static cudaStream_t sA = 0, sL = 0;
    static cudaEvent_t evF, evA, evX0, evX1, evL0, evL1;
    static int init_done = 0;
    if (!init_done) {
        cudaFuncSetAttribute(k_gemm_mma, cudaFuncAttributeMaxDynamicSharedMemorySize,
                             3 * STAGE_B);
        cudaFuncSetAttribute(k_lnt, cudaFuncAttributeMaxDynamicSharedMemorySize,
                             8 * LBUF * 4);
        cudaFuncSetAttribute(k_sink_colT, cudaFuncAttributeMaxDynamicSharedMemorySize,
                             NN * CP * 4);
        cudaFuncSetAttribute(k_xlocal, cudaFuncAttributeMaxDynamicSharedMemorySize,
                             XL_SMEM);
        cudaStreamCreateWithFlags(&sA, cudaStreamNonBlocking);
        cudaStreamCreateWithFlags(&sL, cudaStreamNonBlocking);
        cudaEventCreateWithFlags(&evF, cudaEventDisableTiming);
        cudaEventCreateWithFlags(&evA, cudaEventDisableTiming);
        cudaEventCreateWithFlags(&evX0, cudaEventDisableTiming);
        cudaEventCreateWithFlags(&evX1, cudaEventDisableTiming);
        cudaEventCreateWithFlags(&evL0, cudaEventDisableTiming);
        cudaEventCreateWithFlags(&evL1, cudaEventDisableTiming);
        init_done = 1;
    }

    // Fork A-path onto sA
    cudaEventRecord(evF, 0);
    cudaStreamWaitEvent(sA, evF, 0);
    k_sink_row<<<NN, 256, 0, sA>>>(A_logits);
    k_sink_colT<<<32, 256, NN * CP * 4, sA>>>();
    cudaEventRecord(evA, sA);

    // X-path on origin stream, split by b-halves
    k_wsink<<<NN, 256>>>(W1, WV);
    k_xlocal<<<NN, 128, XL_SMEM>>>(x, 0);
    cudaEventRecord(evX0, 0);
    k_xlocal<<<NN, 128, XL_SMEM>>>(x, 128);
    cudaEventRecord(evX1, 0);

    // LN halves on sL, each gated on its xlocal half
    cudaStreamWaitEvent(sL, evX0, 0);
    k_lnt<<<dim3(128, 8), 256, 8 * LBUF * 4, sL>>>(gamma2, beta2, 0);
    cudaEventRecord(evL0, sL);
    cudaStreamWaitEvent(sL, evX1, 0);
    k_lnt<<<dim3(128, 8), 256, 8 * LBUF * 4, sL>>>(gamma2, beta2, 128);
    cudaEventRecord(evL1, sL);

    // GEMM halves on origin stream; h0 needs A-path + lnt_h0, h1 needs lnt_h1
    cudaStreamWaitEvent(0, evA, 0);
    cudaStreamWaitEvent(0, evL0, 0);
    k_gemm_mma<<<dim3(64, 8), 256, 3 * STAGE_B>>>(out, 0);
    cudaStreamWaitEvent(0, evL1, 0);
    k_gemm_mma<<<dim3(64, 8), 256, 3 * STAGE_B>>>(out, 64);
}

// round 17
// speedup vs baseline: 1.0888x; 1.0888x over previous
#include <cuda_runtime.h>
#include <cuda_bf16.h>
#include <cuda_fp16.h>
#include <math.h>
#include <stdint.h>

// Problem constants
#define NB 256        // batch B
#define NN 1024       // N
#define NK 64         // K
#define INV_TEMP 5.0f // 1/0.2
#define LN_EPS 1e-5f
#define A_SCALE 4096.0f
#define A_INV_SCALE 2.44140625e-4f
#define WP_SCALE 16384.0f
#define WP_INV (1.0f / 16384.0f)
#define C_N 9.765625e-4f   // 1/1024 exact
#define C_K 0.015625f      // 1/64 exact

// Scratch (static device globals; allocation inside kernel_launch is forbidden)
static __device__ float g_S[NN * NN];                    // row-stochastic P 4 MB
static __device__ __half g_WT[(size_t)NN * NK * NK];     // (W - 1/64)^T *16384 fp16 [n][o][i] 8 MB
static __device__ __half g_XLh[(size_t)NB * NN * NK];    // x_local fp16 [b][n][k] 32 MB
static __device__ __half g_Yh[(size_t)NB * NK * NN];     // Y fp16 [r][m] 32 MB
static __device__ __half g_STh[NN * NN];                 // (A - 1/1024)^T * 4096, fp16 [n][m] 2 MB
static __device__ float g_SY[NB * NK];                   // per-row sums of Y (exact fp32)

// ============================ PTX helpers (sm_80-era only!) ============================
__device__ __forceinline__ uint32_t smem_u32(const void* p) {
    uint32_t a;
    asm("{ .reg .u64 t; cvta.to.shared.u64 t, %1; cvt.u32.u64 %0, t; }" : "=r"(a) : "l"(p));
    return a;
}
__device__ __forceinline__ void cpa16(uint32_t s, const void* g) {
    asm volatile("cp.async.cg.shared.global [%0], [%1], 16;" :: "r"(s), "l"(g));
}
__device__ __forceinline__ void ldm4(uint32_t* r, uint32_t a) {
    asm volatile("ldmatrix.sync.aligned.m8n8.x4.shared.b16 {%0,%1,%2,%3}, [%4];"
                 : "=r"(r[0]), "=r"(r[1]), "=r"(r[2]), "=r"(r[3]) : "r"(a));
}
__device__ __forceinline__ void mma_fp16(float* d, const uint32_t* a, const uint32_t* b) {
    asm volatile(
        "mma.sync.aligned.m16n8k16.row.col.f32.f16.f16.f32 "
        "{%0,%1,%2,%3}, {%4,%5,%6,%7}, {%8,%9}, {%0,%1,%2,%3};"
        : "+f"(d[0]), "+f"(d[1]), "+f"(d[2]), "+f"(d[3])
        : "r"(a[0]), "r"(a[1]), "r"(a[2]), "r"(a[3]), "r"(b[0]), "r"(b[1]));
}

// ---------------------------------------------------------------------------
// Kernel 1: row pass. P[row] = exp(logits/T) / rowsum — linear domain, __expf.
// ---------------------------------------------------------------------------
__global__ void k_sink_row(const float* __restrict__ logits) {
    const int row = blockIdx.x;
    const int t = threadIdx.x;
    const float* rp = logits + (size_t)row * NN;
    float e[4];
    float acc = 0.f;
#pragma unroll
    for (int q = 0; q < 4; ++q) {
        e[q] = __expf(rp[t + 256 * q] * INV_TEMP);
        acc += e[q];
    }
    __shared__ float red[256];
    red[t] = acc;
    __syncthreads();
    for (int s = 128; s > 0; s >>= 1) {
        if (t < s) red[t] += red[t + s];
        __syncthreads();
    }
    const float rinv = 1.0f / red[0];
    float* op = g_S + (size_t)row * NN;
#pragma unroll
    for (int q = 0; q < 4; ++q) op[t + 256 * q] = e[q] * rinv;
}

// ---------------------------------------------------------------------------
// Kernel 2: column normalize + emit STh[n][m] = (P[m][n]/colsum - 1/1024)*4096
// directly (transposed, fp16) via a 135 KB smem buffer. No exp at all.
// ---------------------------------------------------------------------------
#define CP 33
__global__ void __launch_bounds__(256) k_sink_colT() {
    extern __shared__ float buf[];  // [1024][CP]
    const int c0 = blockIdx.x * 32;
    const int t = threadIdx.x;
    const int c = t & 31, ry = t >> 5;
    float csum = 0.f;
    for (int m = ry; m < NN; m += 8) {
        float v = g_S[(size_t)m * NN + c0 + c];
        buf[m * CP + c] = v;
        csum += v;
    }
    __shared__ float ss[8][32];
    __shared__ float cinv[32];
    ss[ry][c] = csum;
    __syncthreads();
    if (t < 32) {
        float S = 0.f;
#pragma unroll
        for (int q = 0; q < 8; ++q) S += ss[q][t];
        cinv[t] = 1.0f / S;
    }
    __syncthreads();
    const int w = t >> 5, L = t & 31;
#pragma unroll
    for (int j = 0; j < 4; ++j) {
        const int cc = w * 4 + j;
        const float ci = cinv[cc] * A_SCALE;  // STh = P*ci - 4  (A_SCALE/1024 = 4)
        __half2* op = (__half2*)(g_STh + (size_t)(c0 + cc) * NN);
#pragma unroll
        for (int q = 0; q < 16; ++q) {
            const int m = 2 * L + 64 * q;
            float a = buf[m * CP + cc] * ci - 4.0f;
            float b = buf[(m + 1) * CP + cc] * ci - 4.0f;
            op[m >> 1] = __floats2half2_rn(a, b);
        }
    }
}

// ---------------------------------------------------------------------------
// Kernel 3: per-block sinkhorn of W1.W_V, linear domain (__expf once, 2 rcps).
// Emits W'^T = (W - 1/64)*WP_SCALE fp16 [n][o][i].
// ---------------------------------------------------------------------------
__global__ void k_wsink(const float* __restrict__ W1, const float* __restrict__ WV) {
    const int n = blockIdx.x;
    const int t = threadIdx.x;
    __shared__ float L[64][65];
    __shared__ float w1[8];
    __shared__ float rinv[64], cinv[64];
    __shared__ float redc[4][64];
    if (t < 8) w1[t] = W1[n * 8 + t];
    __syncthreads();
#pragma unroll
    for (int q = 0; q < 16; ++q) {
        int idx = t + 256 * q;
        float acc = 0.f;
#pragma unroll
        for (int k = 0; k < 8; ++k) acc += w1[k] * WV[k * 4096 + idx];
        L[idx >> 6][idx & 63] = __expf(acc * INV_TEMP);
    }
    __syncthreads();
    {
        const int r = t >> 2, j0 = (t & 3) * 16;
        float s = 0.f;
#pragma unroll
        for (int e = 0; e < 16; ++e) s += L[r][j0 + e];
        s += __shfl_xor_sync(0xffffffffu, s, 1);
        s += __shfl_xor_sync(0xffffffffu, s, 2);
        if ((t & 3) == 0) rinv[r] = 1.0f / s;
    }
    __syncthreads();
    {
        const int o = t & 63, p = t >> 6;
        float cs = 0.f;
#pragma unroll
        for (int e = 0; e < 16; ++e) {
            const int d = p * 16 + e;
            float f = L[d][o] * rinv[d];
            L[d][o] = f;
            cs += f;
        }
        redc[p][o] = cs;
    }
    __syncthreads();
    if (t < 64)
        cinv[t] = 1.0f / ((redc[0][t] + redc[1][t]) + (redc[2][t] + redc[3][t]));
    __syncthreads();
    __half* wt = g_WT + (size_t)n * 4096;
#pragma unroll
    for (int q = 0; q < 16; ++q) {
        int idx = t + 256 * q;
        int o = idx >> 6, d = idx & 63;
        wt[idx] = __float2half((L[d][o] * cinv[o] - C_K) * WP_SCALE);
    }
}

// ---------------------------------------------------------------------------
// Kernel 4: x_local = sx/64 + (x@W'^T)/16384 via fp16 MMA. One n per block,
// ALL 256 b rows in one pass: every global load issued before the single
// sync (MLP ~16/thread), so DRAM latency is paid once per block. 8 warps,
// warp tile 32(b) x 64(k).
// smem: Xs fp16 [256][72] | Ws fp16 [64][72] | sxs[256] fp32  (= 47104 B)
// ---------------------------------------------------------------------------
#define XL_SMEM (256 * 72 * 2 + 64 * 72 * 2 + 256 * 4)
__global__ void __launch_bounds__(256) k_xlocal(const float* __restrict__ x) {
    extern __shared__ char dsm[];
    __half* Xs = (__half*)dsm;                 // [256][72]
    __half* Ws = Xs + 256 * 72;                // [64][72]
    float* sxs = (float*)(Ws + 64 * 72);       // [256]

    const int n = blockIdx.x;
    const int t = threadIdx.x;
    const int L = t & 31, w = t >> 5;

    // WT tile once per block
    {
        const __half* wp = g_WT + (size_t)n * 4096;
#pragma unroll
        for (int q = 0; q < 2; ++q) {
            int u = t + 256 * q;
            int row = u >> 3, c8 = (u & 7) * 8;
            *(uint4*)(Ws + row * 72 + c8) = *(const uint4*)(wp + u * 8);
        }
    }

    // X: 4 threads per row, 4 row-passes — 16 independent LDG.128 per thread.
    {
        const int rbase = t >> 2, c0 = (t & 3) * 16;
#pragma unroll
        for (int q = 0; q < 4; ++q) {
            const int row = rbase + 64 * q;
            const float* xp = x + (size_t)row * (NN * NK) + n * NK + c0;
            float4 v0 = *(const float4*)(xp + 0);
            float4 v1 = *(const float4*)(xp + 4);
            float4 v2 = *(const float4*)(xp + 8);
            float4 v3 = *(const float4*)(xp + 12);
            float s = ((v0.x + v0.y) + (v0.z + v0.w)) + ((v1.x + v1.y) + (v1.z + v1.w)) +
                      ((v2.x + v2.y) + (v2.z + v2.w)) + ((v3.x + v3.y) + (v3.z + v3.w));
            __half2* xs = (__half2*)(Xs + row * 72 + c0);
            xs[0] = __floats2half2_rn(v0.x, v0.y);
            xs[1] = __floats2half2_rn(v0.z, v0.w);
            xs[2] = __floats2half2_rn(v1.x, v1.y);
            xs[3] = __floats2half2_rn(v1.z, v1.w);
            xs[4] = __floats2half2_rn(v2.x, v2.y);
            xs[5] = __floats2half2_rn(v2.z, v2.w);
            xs[6] = __floats2half2_rn(v3.x, v3.y);
            xs[7] = __floats2half2_rn(v3.z, v3.w);
            s += __shfl_xor_sync(0xffffffffu, s, 1);
            s += __shfl_xor_sync(0xffffffffu, s, 2);
            if ((t & 3) == 0) sxs[row] = s;
        }
    }
    __syncthreads();

    // MMA: warp w owns b rows [w*32, w*32+32), all 64 k.
    const int m0 = w * 32;
    const uint32_t xb = smem_u32(Xs), wb = smem_u32(Ws);
    const uint32_t a_l = xb + (uint32_t)((m0 + (L & 15)) * 144 + (L >> 4) * 16);
    const uint32_t b_l = wb + (uint32_t)(((L & 7) + ((L & 16) ? 8 : 0)) * 144 +
                                         ((L & 8) ? 16 : 0));
    float acc[2][8][4] = {};
#pragma unroll
    for (int ks = 0; ks < 4; ++ks) {
        uint32_t ah[2][4], bh[4][4];
#pragma unroll
        for (int mt = 0; mt < 2; ++mt)
            ldm4(ah[mt], a_l + ks * 32 + mt * (16 * 144));
#pragma unroll
        for (int bj = 0; bj < 4; ++bj)
            ldm4(bh[bj], b_l + ks * 32 + bj * (16 * 144));
#pragma unroll
        for (int mt = 0; mt < 2; ++mt)
#pragma unroll
            for (int nj = 0; nj < 8; ++nj)
                mma_fp16(acc[mt][nj], ah[mt], &bh[nj >> 1][(nj & 1) * 2]);
    }

    // Epilogue: xl = acc*WP_INV + sx/64, fp16 [b][n][k]
    const int r = L >> 2;
#pragma unroll
    for (int mt = 0; mt < 2; ++mt) {
        const int b0 = m0 + mt * 16 + r;
        const float sx0 = sxs[b0] * C_K, sx1 = sxs[b0 + 8] * C_K;
        __half* xl0 = g_XLh + ((size_t)b0 * NN + n) * NK;
        __half* xl1 = xl0 + (size_t)8 * NN * NK;
#pragma unroll
        for (int nj = 0; nj < 8; ++nj) {
            const int k = nj * 8 + (L & 3) * 2;
            *(__half2*)(xl0 + k) =
                __floats2half2_rn(acc[mt][nj][0] * WP_INV + sx0, acc[mt][nj][1] * WP_INV + sx0);
            *(__half2*)(xl1 + k) =
                __floats2half2_rn(acc[mt][nj][2] * WP_INV + sx1, acc[mt][nj][3] * WP_INV + sx1);
        }
    }
}

// ---------------------------------------------------------------------------
// Kernel 5: layernorm over n (per (b,k)) + transpose, k-chunk 8 (33 KB smem,
// 6 blocks/SM). Reads fp16 XL, emits fp16 Y [r][m] + exact fp32 row sums.
// ---------------------------------------------------------------------------
#define LBUF 1025
__global__ void __launch_bounds__(256) k_lnt(const float* __restrict__ gamma2,
                                             const float* __restrict__ beta2) {
    extern __shared__ float buf[];  // [8][LBUF]
    const int b = blockIdx.x;
    const int k0 = blockIdx.y * 8;
    const int t = threadIdx.x;
    const __half* base = g_XLh + (size_t)b * NN * NK + k0;
#pragma unroll
    for (int q = 0; q < 4; ++q) {
        const int nn = t + 256 * q;
        uint4 v = *(const uint4*)(base + (size_t)nn * NK);
        const __half2* h = (const __half2*)&v;
#pragma unroll
        for (int j = 0; j < 4; ++j) {
            float2 f = __half22float2(h[j]);
            buf[(2 * j) * LBUF + nn] = f.x;
            buf[(2 * j + 1) * LBUF + nn] = f.y;
        }
    }
    __syncthreads();
    __shared__ float ps[32][9], ps2[32][9], mu[8], rs[8];
    {
        const int kc = t & 7, nr = t >> 3;
        float s = 0.f, s2 = 0.f;
        for (int nn = nr; nn < NN; nn += 32) {
            float v = buf[kc * LBUF + nn];
            s += v;
            s2 += v * v;
        }
        ps[nr][kc] = s;
        ps2[nr][kc] = s2;
    }
    __syncthreads();
    if (t < 8) {
        float S = 0.f, S2 = 0.f;
#pragma unroll
        for (int q = 0; q < 32; ++q) { S += ps[q][t]; S2 += ps2[q][t]; }
        float m = S * (1.0f / NN);
        mu[t] = m;
        rs[t] = rsqrtf(S2 * (1.0f / NN) - m * m + LN_EPS);
    }
    __syncthreads();
    const int L = t & 31, w = t >> 5;
    const float m = mu[w], r = rs[w];
    __half2* yp = (__half2*)(g_Yh + (size_t)(b * NK + k0 + w) * NN);
    float sy = 0.f;
#pragma unroll
    for (int q = 0; q < 16; ++q) {
        const int nn = 2 * L + 64 * q;
        float2 g = *(const float2*)(gamma2 + nn);
        float2 bt = *(const float2*)(beta2 + nn);
        float v0 = (buf[w * LBUF + nn] - m) * r * g.x + bt.x;
        float v1 = (buf[w * LBUF + nn + 1] - m) * r * g.y + bt.y;
        sy += v0 + v1;
        yp[nn >> 1] = __floats2half2_rn(v0, v1);
    }
#pragma unroll
    for (int off = 16; off; off >>= 1) sy += __shfl_xor_sync(0xffffffffu, sy, off);
    if (L == 0) g_SY[b * NK + k0 + w] = sy;
}

// ---------------------------------------------------------------------------
// Kernel 6: single-pass fp16 tensor-core GEMM, 3-stage cp.async pipeline.
//   D[r][n] = sum_m Yh[r][m] * STh[n][m];  out = D/A_SCALE + SY[r]/1024.
// Single 1024-CTA launch (128 r-tiles x 8 n-tiles).
// ---------------------------------------------------------------------------
#define T_ROWB 144
#define TILE_B (128 * T_ROWB)
#define STAGE_B (2 * TILE_B)
#define OFF_Y 0u
#define OFF_S ((uint32_t)TILE_B)

__device__ __forceinline__ void g_load_stage(uint32_t st, int r0, int n0, int m0, int t) {
    for (int i = t; i < 1024; i += 256) {
        const int row = i >> 3, q = i & 7;
        const uint32_t so = (uint32_t)(row * T_ROWB + q * 16);
        cpa16(st + OFF_Y + so, g_Yh + (size_t)(r0 + row) * NN + m0 + q * 8);
        cpa16(st + OFF_S + so, g_STh + (size_t)(n0 + row) * NN + m0 + q * 8);
    }
}

__global__ void __launch_bounds__(256) k_gemm_mma(float* __restrict__ out) {
    extern __shared__ char dsm[];
    const int t = threadIdx.x;
    const int r0 = blockIdx.x * 128;
    const int n0 = blockIdx.y * 128;
    __shared__ float s_sy[128];
    if (t < 128) s_sy[t] = g_SY[r0 + t] * C_N;
    const uint32_t sb = smem_u32(dsm);

    g_load_stage(sb, r0, n0, 0, t);
    asm volatile("cp.async.commit_group;" ::: "memory");
    g_load_stage(sb + STAGE_B, r0, n0, 64, t);
    asm volatile("cp.async.commit_group;" ::: "memory");
    g_load_stage(sb + 2 * STAGE_B, r0, n0, 128, t);
    asm volatile("cp.async.commit_group;" ::: "memory");

    const int L = t & 31, w = t >> 5;
    const int wr = (w >> 1) * 32;
    const int wn = (w & 1) * 64;
    const uint32_t a_l = (uint32_t)((wr + (L & 15)) * T_ROWB + ((L >> 4) * 8) * 2);
    const uint32_t b_l = (uint32_t)((wn + (L & 7) + ((L & 16) ? 8 : 0)) * T_ROWB + ((L & 8) ? 16 : 0));

    float acc[2][8][4] = {};
    int stg = 0;

#pragma unroll 1
    for (int c = 0; c < 16; ++c) {
        if (c < 14)       asm volatile("cp.async.wait_group 2;" ::: "memory");
        else if (c == 14) asm volatile("cp.async.wait_group 1;" ::: "memory");
        else              asm volatile("cp.async.wait_group 0;" ::: "memory");
        __syncthreads();
        const uint32_t st = sb + (uint32_t)stg * STAGE_B;
#pragma unroll
        for (int ks = 0; ks < 4; ++ks) {
            uint32_t ah[2][4], bh[4][4];
            const uint32_t ka = st + a_l + ks * 32;
            const uint32_t kb = st + b_l + ks * 32;
#pragma unroll
            for (int mt = 0; mt < 2; ++mt)
                ldm4(ah[mt], ka + OFF_Y + mt * (16 * T_ROWB));
#pragma unroll
            for (int bj = 0; bj < 4; ++bj)
                ldm4(bh[bj], kb + OFF_S + bj * (16 * T_ROWB));
#pragma unroll
            for (int mt = 0; mt < 2; ++mt)
#pragma unroll
                for (int nj = 0; nj < 8; ++nj)
                    mma_fp16(acc[mt][nj], ah[mt], &bh[nj >> 1][(nj & 1) * 2]);
        }
        __syncthreads();
        if (c + 3 < 16) {
            g_load_stage(st, r0, n0, (c + 3) * 64, t);
            asm volatile("cp.async.commit_group;" ::: "memory");
        }
        stg = (stg == 2) ? 0 : stg + 1;
    }

    // Epilogue: acc -> smem [n][r], then coalesced float4 STG.
    float* so = (float*)dsm;
#pragma unroll
    for (int mt = 0; mt < 2; ++mt)
#pragma unroll
        for (int nj = 0; nj < 8; ++nj) {
            const int rl = wr + mt * 16 + (L >> 2);
            const int nl = wn + nj * 8 + (L & 3) * 2;
            so[nl * 132 + rl]           = acc[mt][nj][0];
            so[(nl + 1) * 132 + rl]     = acc[mt][nj][1];
            so[nl * 132 + rl + 8]       = acc[mt][nj][2];
            so[(nl + 1) * 132 + rl + 8] = acc[mt][nj][3];
        }
    __syncthreads();
    for (int i = t; i < 4096; i += 256) {
        const int n = i >> 5;
        const int rq = (i & 31) * 4;
        float4 v;
        v.x = so[n * 132 + rq]     * A_INV_SCALE + s_sy[rq];
        v.y = so[n * 132 + rq + 1] * A_INV_SCALE + s_sy[rq + 1];
        v.z = so[n * 132 + rq + 2] * A_INV_SCALE + s_sy[rq + 2];
        v.w = so[n * 132 + rq + 3] * A_INV_SCALE + s_sy[rq + 3];
        const int r = r0 + rq;
        *(float4*)(out + (size_t)(r >> 6) * (NN * NK) + (size_t)(n0 + n) * NK + (r & 63)) = v;
    }
}

// ---------------------------------------------------------------------------
// Launch: R15 serial topology + ONE change: the independent A-path
// (sink_row -> colT) forked to a side stream, hidden under wsink/xlocal,
// joined via event before the GEMM.
// ---------------------------------------------------------------------------
extern "C" void kernel_launch(void* const* d_in, const int* in_sizes, int n_in,
                              void* d_out, int out_size) {
    (void)in_sizes; (void)n_in; (void)out_size;
    const float* x        = (const float*)d_in[0];  // [B, N*K]
    const float* A_logits = (const float*)d_in[1];  // [N, N]
    const float* W1       = (const float*)d_in[2];  // [N, 8]
    const float* WV       = (const float*)d_in[3];  // [8, K, K]
    const float* gamma2   = (const float*)d_in[4];  // [N]
    const float* beta2    = (const float*)d_in[5];  // [N]
    float* out = (float*)d_out;

    static cudaStream_t sA = 0;
    static cudaEvent_t evF, evA;
    static int init_done = 0;
    if (!init_done) {
        cudaFuncSetAttribute(k_gemm_mma, cudaFuncAttributeMaxDynamicSharedMemorySize,
                             3 * STAGE_B);
        cudaFuncSetAttribute(k_lnt, cudaFuncAttributeMaxDynamicSharedMemorySize,
                             8 * LBUF * 4);
        cudaFuncSetAttribute(k_sink_colT, cudaFuncAttributeMaxDynamicSharedMemorySize,
                             NN * CP * 4);
        cudaFuncSetAttribute(k_xlocal, cudaFuncAttributeMaxDynamicSharedMemorySize,
                             XL_SMEM);
        cudaStreamCreateWithFlags(&sA, cudaStreamNonBlocking);
        cudaEventCreateWithFlags(&evF, cudaEventDisableTiming);
        cudaEventCreateWithFlags(&evA, cudaEventDisableTiming);
        init_done = 1;
    }

    // Fork A-path (independent of X-path) onto side stream
    cudaEventRecord(evF, 0);
    cudaStreamWaitEvent(sA, evF, 0);
    k_sink_row<<<NN, 256, 0, sA>>>(A_logits);
    k_sink_colT<<<32, 256, NN * CP * 4, sA>>>();
    cudaEventRecord(evA, sA);

    // X-path, serial on origin stream (R15 topology)
    k_wsink<<<NN, 256>>>(W1, WV);
    k_xlocal<<<NN, 256, XL_SMEM>>>(x);
    k_lnt<<<dim3(NB, 8), 256, 8 * LBUF * 4>>>(gamma2, beta2);

    // Join A-path, then the single full-size GEMM
    cudaStreamWaitEvent(0, evA, 0);
    k_gemm_mma<<<dim3(128, 8), 256, 3 * STAGE_B>>>(out);
}